// round 17
// baseline (speedup 1.0000x reference)
#include <cuda_runtime.h>
#include <cuda_bf16.h>
#include <cstdint>

// Problem constants
#define M_ROWS   4096          // b*NT*2*NO = 16*8*32
#define K_VIS    2048
#define FEAT     512
#define BT       128           // b*NT
#define NO       16
#define TGT      24
#define N_EDGE   (BT * NO * NO)        // 32768
#define OUT_LOGITS (N_EDGE * TGT)      // 786432

typedef unsigned long long ull;

// Scratch (device globals; referenced ONLY in device code)
// NOTE: g_WrT/g_Ws/g_Wo/g_W2s/g_W2o are stored TRANSPOSED: [TGT][FEAT]
__device__ __align__(16) float g_h1[M_ROWS * FEAT];
__device__ __align__(16) float g_WrT[2 * TGT * FEAT];  // wr halves transposed
__device__ __align__(16) float g_Ws[TGT * FEAT];     // (wf @ wr_top)^T
__device__ __align__(16) float g_Wo[TGT * FEAT];     // (wf @ wr_bot)^T
__device__ __align__(16) float g_W2s[TGT * FEAT];    // (w2 @ Ws)^T
__device__ __align__(16) float g_W2o[TGT * FEAT];    // (w2 @ Wo)^T
__device__ float g_bs[TGT];            // bf @ wr_top
__device__ float g_bo[TGT];            // bf @ wr_bot + br
__device__ float g_bs2[TGT];           // b2 @ Ws + bs
__device__ float g_bo2[TGT];           // b2 @ Wo + bo
__device__ __align__(16) float g_sout[BT * NO * TGT];
__device__ __align__(16) float g_oout[BT * NO * TGT];
__device__ float g_p1[128];
__device__ float g_p2[128];
__device__ int   g_tgt_is64;
__device__ unsigned g_ctr;             // combine_loss completion counter

// ---------------------------------------------------------------------------
// PTX helpers
// ---------------------------------------------------------------------------
__device__ __forceinline__ unsigned su32(const void* p) {
    return (unsigned)__cvta_generic_to_shared(p);
}
__device__ __forceinline__ unsigned packbf(float f0, float f1) {
    unsigned r;
    asm("cvt.rn.bf16x2.f32 %0, %1, %2;" : "=r"(r) : "f"(f1), "f"(f0));
    return r;
}
__device__ __forceinline__ void ldsm_x4(unsigned& r0, unsigned& r1,
                                        unsigned& r2, unsigned& r3,
                                        unsigned addr) {
    asm volatile("ldmatrix.sync.aligned.m8n8.x4.shared.b16 {%0,%1,%2,%3}, [%4];"
                 : "=r"(r0), "=r"(r1), "=r"(r2), "=r"(r3) : "r"(addr));
}
__device__ __forceinline__ void ldsm_x4t(unsigned& r0, unsigned& r1,
                                         unsigned& r2, unsigned& r3,
                                         unsigned addr) {
    asm volatile("ldmatrix.sync.aligned.m8n8.x4.trans.shared.b16 {%0,%1,%2,%3}, [%4];"
                 : "=r"(r0), "=r"(r1), "=r"(r2), "=r"(r3) : "r"(addr));
}
__device__ __forceinline__ void mma16816(float* c, const unsigned* a,
                                         const unsigned* b) {
    asm volatile(
        "mma.sync.aligned.m16n8k16.row.col.f32.bf16.bf16.f32 "
        "{%0,%1,%2,%3},{%4,%5,%6,%7},{%8,%9},{%0,%1,%2,%3};"
        : "+f"(c[0]), "+f"(c[1]), "+f"(c[2]), "+f"(c[3])
        : "r"(a[0]), "r"(a[1]), "r"(a[2]), "r"(a[3]), "r"(b[0]), "r"(b[1]));
}
__device__ __forceinline__ void split_store(float4 v, void* hp, void* lp) {
    unsigned h01 = packbf(v.x, v.y);
    unsigned h23 = packbf(v.z, v.w);
    float h0 = __uint_as_float(h01 << 16);
    float h1 = __uint_as_float(h01 & 0xffff0000u);
    float h2 = __uint_as_float(h23 << 16);
    float h3 = __uint_as_float(h23 & 0xffff0000u);
    unsigned l01 = packbf(v.x - h0, v.y - h1);
    unsigned l23 = packbf(v.z - h2, v.w - h3);
    *reinterpret_cast<uint2*>(hp) = make_uint2(h01, h23);
    *reinterpret_cast<uint2*>(lp) = make_uint2(l01, l23);
}
__device__ __forceinline__ void ffma2(ull& d, ull a, ull b) {
    asm("fma.rn.f32x2 %0, %1, %2, %0;" : "+l"(d) : "l"(a), "l"(b));
}
__device__ __forceinline__ void unpack2(float& lo, float& hi, ull v) {
    asm("mov.b64 {%0, %1}, %2;" : "=f"(lo), "=f"(hi) : "l"(v));
}

// ---------------------------------------------------------------------------
// GEMM1 via tensor cores (bf16 split, fp32-accurate).
// BM 64 (grid 256 blocks, 2 CTAs/SM) — k-order identical to the proven
// BM=128 version; only block decomposition changes.
// g_h1 = relu(src @ w1 + b1),  M=4096, N=512, K=2048.
// ---------------------------------------------------------------------------
#define BM 64
#define BN 128
#define CK 32
#define APAD 40
#define BPAD 136

__global__ __launch_bounds__(256, 2) void mma_gemm_relu(
    const float* __restrict__ A, const float* __restrict__ B,
    const float* __restrict__ bias)
{
    __shared__ __align__(16) __nv_bfloat16 sAh[BM][APAD];
    __shared__ __align__(16) __nv_bfloat16 sAl[BM][APAD];
    __shared__ __align__(16) __nv_bfloat16 sBh[CK][BPAD];
    __shared__ __align__(16) __nv_bfloat16 sBl[CK][BPAD];

    const int tid = threadIdx.x;
    const int lane = tid & 31;
    const int wid = tid >> 5;
    const int wm = wid & 1;        // 32 rows each
    const int wn = wid >> 1;       // 32 cols each
    const int bm = blockIdx.y * BM;
    const int bn = blockIdx.x * BN;

    // A chunk 64x32 fp32 = 512 float4; 256 threads x 2 iters
    const int arow = tid >> 3;          // 0..31
    const int acol = (tid & 7) * 4;
    // B chunk 32x128 fp32 = 1024 float4; 256 threads x 4 iters
    const int brow = tid >> 5;
    const int bcol = (tid & 31) * 4;

    const float* Ap = A + (size_t)(bm + arow) * K_VIS + acol;
    const float* Bp = B + (size_t)brow * FEAT + bn + bcol;

    unsigned aAddrH[2], aAddrL[2];
#pragma unroll
    for (int mi = 0; mi < 2; mi++) {
        const int r = wm * 32 + mi * 16 + (lane & 15);
        const int c = (lane >> 4) * 8;
        aAddrH[mi] = su32(&sAh[r][c]);
        aAddrL[mi] = su32(&sAl[r][c]);
    }
    unsigned bAddrH[2], bAddrL[2];
#pragma unroll
    for (int nh = 0; nh < 2; nh++) {
        const int r = (lane & 15);
        const int c = wn * 32 + nh * 16 + (lane >> 4) * 8;
        bAddrH[nh] = su32(&sBh[r][c]);
        bAddrL[nh] = su32(&sBl[r][c]);
    }

    float acc[2][4][4];
#pragma unroll
    for (int mi = 0; mi < 2; mi++)
#pragma unroll
        for (int ni = 0; ni < 4; ni++)
#pragma unroll
            for (int q = 0; q < 4; q++) acc[mi][ni][q] = 0.0f;

    float4 aS[2], bS[4];
#pragma unroll
    for (int j = 0; j < 2; j++)
        aS[j] = *reinterpret_cast<const float4*>(Ap + (size_t)j * 32 * K_VIS);
#pragma unroll
    for (int j = 0; j < 4; j++)
        bS[j] = *reinterpret_cast<const float4*>(Bp + (size_t)j * 8 * FEAT);
#pragma unroll
    for (int j = 0; j < 2; j++)
        split_store(aS[j], &sAh[arow + j * 32][acol], &sAl[arow + j * 32][acol]);
#pragma unroll
    for (int j = 0; j < 4; j++)
        split_store(bS[j], &sBh[brow + j * 8][bcol], &sBl[brow + j * 8][bcol]);
    __syncthreads();

    const int nCh = K_VIS / CK;    // 64
    for (int ch = 0; ch < nCh; ch++) {
        const bool more = (ch + 1 < nCh);
        if (more) {
            const float* Ap2 = Ap + (ch + 1) * CK;
            const float* Bp2 = Bp + (size_t)(ch + 1) * CK * FEAT;
#pragma unroll
            for (int j = 0; j < 2; j++)
                aS[j] = *reinterpret_cast<const float4*>(Ap2 + (size_t)j * 32 * K_VIS);
#pragma unroll
            for (int j = 0; j < 4; j++)
                bS[j] = *reinterpret_cast<const float4*>(Bp2 + (size_t)j * 8 * FEAT);
        }

#pragma unroll
        for (int ks = 0; ks < 2; ks++) {
            const unsigned koff = ks * 16 * 2;
            unsigned ah[2][4], al[2][4], bh[2][4], bl[2][4];
#pragma unroll
            for (int mi = 0; mi < 2; mi++) {
                ldsm_x4(ah[mi][0], ah[mi][1], ah[mi][2], ah[mi][3],
                        aAddrH[mi] + koff);
                ldsm_x4(al[mi][0], al[mi][1], al[mi][2], al[mi][3],
                        aAddrL[mi] + koff);
            }
            const unsigned krow = ks * 16 * (BPAD * 2);
#pragma unroll
            for (int nh = 0; nh < 2; nh++) {
                ldsm_x4t(bh[nh][0], bh[nh][1], bh[nh][2], bh[nh][3],
                         bAddrH[nh] + krow);
                ldsm_x4t(bl[nh][0], bl[nh][1], bl[nh][2], bl[nh][3],
                         bAddrL[nh] + krow);
            }
#pragma unroll
            for (int mi = 0; mi < 2; mi++)
#pragma unroll
                for (int ni = 0; ni < 4; ni++) {
                    const int nh = ni >> 1;
                    const int sel = (ni & 1) * 2;
                    mma16816(acc[mi][ni], ah[mi], &bh[nh][sel]);
                    mma16816(acc[mi][ni], ah[mi], &bl[nh][sel]);
                    mma16816(acc[mi][ni], al[mi], &bh[nh][sel]);
                }
        }

        // Barrier 1: all warps done reading smem (ldsm) before overwrite
        __syncthreads();
        if (more) {
#pragma unroll
            for (int j = 0; j < 2; j++)
                split_store(aS[j], &sAh[arow + j * 32][acol],
                            &sAl[arow + j * 32][acol]);
#pragma unroll
            for (int j = 0; j < 4; j++)
                split_store(bS[j], &sBh[brow + j * 8][bcol],
                            &sBl[brow + j * 8][bcol]);
            // Barrier 2: stores visible before next chunk's ldsm
            __syncthreads();
        }
    }

#pragma unroll
    for (int ni = 0; ni < 4; ni++) {
        const int cn = bn + wn * 32 + ni * 8 + (lane & 3) * 2;
        const float2 bv = *reinterpret_cast<const float2*>(&bias[cn]);
#pragma unroll
        for (int mi = 0; mi < 2; mi++) {
            const int r0 = bm + wm * 32 + mi * 16 + (lane >> 2);
            float2 v0, v1;
            v0.x = fmaxf(acc[mi][ni][0] + bv.x, 0.0f);
            v0.y = fmaxf(acc[mi][ni][1] + bv.y, 0.0f);
            v1.x = fmaxf(acc[mi][ni][2] + bv.x, 0.0f);
            v1.y = fmaxf(acc[mi][ni][3] + bv.y, 0.0f);
            *reinterpret_cast<float2*>(&g_h1[(size_t)r0 * FEAT + cn]) = v0;
            *reinterpret_cast<float2*>(&g_h1[(size_t)(r0 + 8) * FEAT + cn]) = v1;
        }
    }
}

// ---------------------------------------------------------------------------
// pre0: blocks [0,32) transpose wr halves -> g_WrT ([TGT][FEAT] per half);
// blocks 32-33 bias1; block 34 tgt dtype detect.
// ---------------------------------------------------------------------------
__global__ __launch_bounds__(256) void pre0_kernel(
    const float* __restrict__ wr, const float* __restrict__ bf,
    const float* __restrict__ br, const int* __restrict__ tgt32)
{
    const int gx = blockIdx.x;
    const int w = threadIdx.x >> 5;
    const int lane = threadIdx.x & 31;

    if (gx < 32) {
        const int half = gx >> 4;
        const int blk = gx & 15;
        const float* wrh = wr + (size_t)half * FEAT * TGT;
        float* dst = g_WrT + (size_t)half * FEAT * TGT;
        // 3072 float4 per half; 192 per block
        const int i4 = blk * 192 + threadIdx.x;
        if (threadIdx.x < 192) {
            const float4 vv = *reinterpret_cast<const float4*>(wrh + (size_t)i4 * 4);
            const int e0 = i4 * 4;
            dst[(e0 % TGT) * FEAT + (e0 / TGT)] = vv.x;
            dst[((e0 + 1) % TGT) * FEAT + ((e0 + 1) / TGT)] = vv.y;
            dst[((e0 + 2) % TGT) * FEAT + ((e0 + 2) / TGT)] = vv.z;
            dst[((e0 + 3) % TGT) * FEAT + ((e0 + 3) / TGT)] = vv.w;
        }
    } else if (gx < 34) {
        const int half = gx - 32;
#pragma unroll
        for (int rep = 0; rep < 3; rep++) {
            const int t = w + rep * 8;
            float s = 0.0f;
#pragma unroll
            for (int i = 0; i < 16; i++) {
                const int f = lane + 32 * i;
                s = fmaf(bf[f], wr[(size_t)(half * FEAT + f) * TGT + t], s);
            }
#pragma unroll
            for (int o = 16; o > 0; o >>= 1)
                s += __shfl_xor_sync(0xFFFFFFFFu, s, o);
            if (lane == 0) {
                if (half == 0) g_bs[t] = s;
                else           g_bo[t] = s + br[t];
            }
        }
    } else {
        if (threadIdx.x == 0) {
            int allzero = 1;
            for (int i = 1; i < 128; i += 2)
                if (tgt32[i] != 0) { allzero = 0; break; }
            g_tgt_is64 = allzero;
        }
    }
}

// ---------------------------------------------------------------------------
// proj4g: warp computes acc[t] over 128-wide k-chunk, WT transposed, coalesced.
// ---------------------------------------------------------------------------
__device__ __forceinline__ void proj4g(
    const float* __restrict__ arow, const float* __restrict__ WT,
    int kc, int lane, float* acc)
{
    const int off = kc * 128 + lane * 4;
    const float4 v = *reinterpret_cast<const float4*>(arow + off);
#pragma unroll
    for (int t = 0; t < TGT; t++) {
        const float4 p =
            *reinterpret_cast<const float4*>(WT + (size_t)t * FEAT + off);
        float s = v.x * p.x;
        s = fmaf(v.y, p.y, s);
        s = fmaf(v.z, p.z, s);
        s = fmaf(v.w, p.w, s);
        acc[t] = s;
    }
#pragma unroll
    for (int t = 0; t < TGT; t++)
#pragma unroll
        for (int o = 16; o > 0; o >>= 1)
            acc[t] += __shfl_xor_sync(0xFFFFFFFFu, acc[t], o);
}

// ---------------------------------------------------------------------------
// pre_A: wproj0 (Ws/Wo from wf @ g_WrT), coalesced, no per-block staging.
// ---------------------------------------------------------------------------
__global__ __launch_bounds__(256) void pre_kernel_A(const float* __restrict__ wf)
{
    __shared__ float sp[8 * TGT];
    const int gx = blockIdx.x;
    const int w = threadIdx.x >> 5;
    const int lane = threadIdx.x & 31;

    const int half = gx >> 8;
    const float* P = g_WrT + (size_t)half * FEAT * TGT;   // [TGT][FEAT]
    float* dst = half ? g_Wo : g_Ws;
    const int f = (gx & 255) * 2 + (w >> 2);
    const int kc = w & 3;

    float acc[TGT];
    proj4g(wf + (size_t)f * FEAT, P, kc, lane, acc);

    if (lane < TGT) sp[w * TGT + lane] = acc[lane];
    __syncthreads();
    if ((w & 3) == 0 && lane < TGT) {
        const float s = sp[w * TGT + lane] + sp[(w + 1) * TGT + lane]
                      + sp[(w + 2) * TGT + lane] + sp[(w + 3) * TGT + lane];
        dst[(size_t)lane * FEAT + f] = s;
    }
}

// ---------------------------------------------------------------------------
// pre_B: wproj1 (W2s/W2o from w2 @ Ws/Wo) + bias2 (unchanged).
// ---------------------------------------------------------------------------
__global__ __launch_bounds__(256) void pre_kernel_B(
    const float* __restrict__ w2, const float* __restrict__ b2)
{
    __shared__ float sp[8 * TGT];
    const int gx = blockIdx.x;
    const int w = threadIdx.x >> 5;
    const int lane = threadIdx.x & 31;

    if (gx < 512) {
        const int half = gx >> 8;
        const float* P = half ? g_Wo : g_Ws;      // [TGT][FEAT]
        float* dst = half ? g_W2o : g_W2s;        // [TGT][FEAT]
        const int f = (gx & 255) * 2 + (w >> 2);
        const int kc = w & 3;

        float acc[TGT];
        proj4g(w2 + (size_t)f * FEAT, P, kc, lane, acc);

        if (lane < TGT) sp[w * TGT + lane] = acc[lane];
        __syncthreads();
        if ((w & 3) == 0 && lane < TGT) {
            const float s = sp[w * TGT + lane] + sp[(w + 1) * TGT + lane]
                          + sp[(w + 2) * TGT + lane]
                          + sp[(w + 3) * TGT + lane];
            dst[(size_t)lane * FEAT + f] = s;
        }
    } else if (gx < 514) {
        const int half = gx - 512;
        const float* W = half ? g_Wo : g_Ws;      // [TGT][FEAT]
#pragma unroll
        for (int rep = 0; rep < 3; rep++) {
            const int t = w + rep * 8;
            float s = 0.0f;
#pragma unroll
            for (int i = 0; i < 16; i++) {
                const int f = lane + 32 * i;
                s = fmaf(b2[f], W[(size_t)t * FEAT + f], s);
            }
#pragma unroll
            for (int o = 16; o > 0; o >>= 1)
                s += __shfl_xor_sync(0xFFFFFFFFu, s, o);
            if (lane == 0) {
                if (half == 0) g_bs2[t] = s + g_bs[t];
                else           g_bo2[t] = s + g_bo[t];
            }
        }
    }
}

// ---------------------------------------------------------------------------
// Rel projection (R16-proven): 128 blocks x 512 threads, 16-way K split.
// ---------------------------------------------------------------------------
__global__ __launch_bounds__(512) void rel_small_kernel()
{
    __shared__ float sh[16][32][TGT];  // 48 KB partials
    const int w = threadIdx.x >> 5;        // k-chunk 0..15
    const int lane = threadIdx.x & 31;
    const int type = blockIdx.x & 1;       // 0 = subject, 1 = object
    const int fp = blockIdx.x >> 1;        // frame pair 0..63
    const int frame = lane >> 4;           // 0..1
    const int n = lane & 15;
    const int row = fp * 64 + frame * 32 + type * NO + n;

    const float* __restrict__ WT = type ? g_W2o : g_W2s;   // [TGT][FEAT]
    const float* __restrict__ hrow = g_h1 + (size_t)row * FEAT + w * 32;
    const float* __restrict__ wbase = WT + w * 32;

    ull accp[TGT];
#pragma unroll
    for (int t = 0; t < TGT; t++) accp[t] = 0ull;

#pragma unroll
    for (int kg = 0; kg < 8; kg++) {
        const float4 v4 = *reinterpret_cast<const float4*>(hrow + kg * 4);
        const ull v01 = reinterpret_cast<const ull*>(&v4)[0];
        const ull v23 = reinterpret_cast<const ull*>(&v4)[1];
#pragma unroll
        for (int t = 0; t < TGT; t++) {
            const float4 w4 = __ldg(reinterpret_cast<const float4*>(
                wbase + (size_t)t * FEAT + kg * 4));
            const ull w01 = reinterpret_cast<const ull*>(&w4)[0];
            const ull w23 = reinterpret_cast<const ull*>(&w4)[1];
            ffma2(accp[t], v01, w01);
            ffma2(accp[t], v23, w23);
        }
    }

#pragma unroll
    for (int t = 0; t < TGT; t++) {
        float lo, hi;
        unpack2(lo, hi, accp[t]);
        sh[w][lane][t] = lo + hi;
    }
    __syncthreads();

    for (int idx = threadIdx.x; idx < 32 * TGT; idx += 512) {
        const int rl = idx / TGT;
        const int t = idx - rl * TGT;
        float v = 0.0f;
#pragma unroll
        for (int ww = 0; ww < 16; ww++) v += sh[ww][rl][t];
        v += type ? g_bo2[t] : g_bs2[t];
        const int fr = rl >> 4;
        const int nn = rl & 15;
        const int bt = fp * 2 + fr;
        float* dst = type ? g_oout : g_sout;
        dst[(size_t)(bt * NO + nn) * TGT + t] = v;
    }
}

// ---------------------------------------------------------------------------
// Fused edge combine + weighted-NLL partials + FINAL loss (last-block pattern).
// ---------------------------------------------------------------------------
__global__ __launch_bounds__(256) void combine_loss_kernel(
    const int* __restrict__ tgt32, float* __restrict__ out,
    float* __restrict__ tgtf, float* __restrict__ loss)
{
    __shared__ float ss[NO * TGT];
    __shared__ float so[NO * TGT];
    __shared__ float sh1[256], sh2[256];
    __shared__ unsigned s_rank;

    const int bt = blockIdx.x;
    if (threadIdx.x < 96) {
        const int o = threadIdx.x * 4;
        *reinterpret_cast<float4*>(&ss[o]) =
            *reinterpret_cast<const float4*>(&g_sout[(size_t)bt * NO * TGT + o]);
        *reinterpret_cast<float4*>(&so[o]) =
            *reinterpret_cast<const float4*>(&g_oout[(size_t)bt * NO * TGT + o]);
    }
    __syncthreads();

    const int e = threadIdx.x;
    const int i = e >> 4;
    const int j = e & 15;
    const int r = bt * 256 + e;

    float lg[TGT];
#pragma unroll
    for (int t = 0; t < TGT; t++) lg[t] = ss[i * TGT + t] + so[j * TGT + t];

    float* op = out + (size_t)r * TGT;
#pragma unroll
    for (int q = 0; q < 6; q++)
        *reinterpret_cast<float4*>(op + q * 4) =
            make_float4(lg[q * 4], lg[q * 4 + 1], lg[q * 4 + 2], lg[q * 4 + 3]);

    float m = lg[0];
#pragma unroll
    for (int t = 1; t < TGT; t++) m = fmaxf(m, lg[t]);
    float s = 0.0f;
#pragma unroll
    for (int t = 0; t < TGT; t++) s += expf(lg[t] - m);
    const int tg = g_tgt_is64 ? tgt32[2 * r] : tgt32[r];
    const float nll = logf(s) + m - lg[tg];
    const float wgt = (tg == 0) ? 1.0f : 100.0f;
    tgtf[r] = (float)tg;

    sh1[e] = wgt * nll;
    sh2[e] = wgt;
    __syncthreads();
    for (int off = 128; off > 0; off >>= 1) {
        if (e < off) {
            sh1[e] += sh1[e + off];
            sh2[e] += sh2[e + off];
        }
        __syncthreads();
    }
    if (e == 0) {
        g_p1[bt] = sh1[0];
        g_p2[bt] = sh2[0];
        __threadfence();
        s_rank = atomicAdd(&g_ctr, 1u);
    }
    __syncthreads();

    // Last block: deterministic final reduction over the 128 partials
    if (s_rank == 127) {
        if (e < 128) {
            sh1[e] = g_p1[e];
            sh2[e] = g_p2[e];
        }
        __syncthreads();
        for (int off = 64; off > 0; off >>= 1) {
            if (e < off) {
                sh1[e] += sh1[e + off];
                sh2[e] += sh2[e + off];
            }
            __syncthreads();
        }
        if (e == 0) {
            loss[0] = sh1[0] / sh2[0];
            g_ctr = 0;   // reset for next graph replay
        }
    }
}

// ---------------------------------------------------------------------------
extern "C" void kernel_launch(void* const* d_in, const int* in_sizes, int n_in,
                              void* d_out, int out_size)
{
    const float* src   = (const float*)d_in[0];
    const int*   tgt32 = (const int*)d_in[1];
    const float* w1 = (const float*)d_in[2];
    const float* b1 = (const float*)d_in[3];
    const float* w2 = (const float*)d_in[4];
    const float* b2 = (const float*)d_in[5];
    const float* wf = (const float*)d_in[6];
    const float* bf = (const float*)d_in[7];
    const float* wr = (const float*)d_in[8];
    const float* br = (const float*)d_in[9];
    float* out = (float*)d_out;

    // Precompute chain: transpose wr + bias1 + detect, then Ws/Wo, then W2s/W2o
    pre0_kernel<<<35, 256>>>(wr, bf, br, tgt32);
    pre_kernel_A<<<512, 256>>>(wf);
    pre_kernel_B<<<514, 256>>>(w2, b2);
    // Tensor-core GEMM1 (BM=64, 256 blocks, 2 CTAs/SM)
    mma_gemm_relu<<<dim3(FEAT / BN, M_ROWS / BM), 256>>>(src, w1, b1);
    // Per-node 24-dim projections
    rel_small_kernel<<<128, 512>>>();
    // edge logits + loss partials + tgt floats + final loss (fused)
    combine_loss_kernel<<<128, 256>>>(tgt32, out, out + OUT_LOGITS,
                                      out + OUT_LOGITS + N_EDGE);
}